// round 1
// baseline (speedup 1.0000x reference)
#include <cuda_runtime.h>
#include <cuda_bf16.h>
#include <cstdint>

// Problem constants (from reference): 50000 nodes, 1.6M edges, 128->64->32->1
#define MAXN 50000
#define MAXE 1600000
#define C1 64
#define C2 32

// Scratch (static __device__ — no allocation allowed)
__device__ float g_dinv[MAXN];
__device__ float g_g1[(size_t)MAXN * C1];
__device__ float g_acc1[(size_t)MAXN * C1];
__device__ float g_g2[(size_t)MAXN * C2];
__device__ float g_acc2[(size_t)MAXN * C2];
__device__ int   g_is64;

// ---------------------------------------------------------------------------
// edge_index dtype detection: reference says int64, but jax without x64 makes
// int32. If int64, the high 32-bit word of each value (vals < 50000) is 0.
__global__ void detect_kernel(const void* __restrict__ ei) {
    if (blockIdx.x == 0 && threadIdx.x == 0) {
        const unsigned int* p = (const unsigned int*)ei;
        int is64 = 1;
        #pragma unroll
        for (int i = 0; i < 32; i++) {
            if (p[2 * i + 1] != 0u) { is64 = 0; break; }
        }
        g_is64 = is64;
    }
}

__device__ __forceinline__ int load_idx(const void* ei, int is64, long long pos) {
    if (is64) return (int)((const long long*)ei)[pos];
    return ((const int*)ei)[pos];
}

// ---------------------------------------------------------------------------
// Degree: deg = (#edges into dst) + 1 (self loop); then dinv = deg^-1/2
__global__ void deg_init_kernel(int nodes) {
    int i = blockIdx.x * blockDim.x + threadIdx.x;
    if (i < nodes) g_dinv[i] = 1.0f;
}

__global__ void deg_count_kernel(const void* __restrict__ ei, int E) {
    int e = blockIdx.x * blockDim.x + threadIdx.x;
    if (e >= E) return;
    int is64 = g_is64;
    int dst = load_idx(ei, is64, (long long)E + e);
    atomicAdd(&g_dinv[dst], 1.0f);
}

__global__ void deg_inv_kernel(int nodes) {
    int i = blockIdx.x * blockDim.x + threadIdx.x;
    if (i < nodes) g_dinv[i] = rsqrtf(g_dinv[i]);
}

// ---------------------------------------------------------------------------
// GEMM1: g1 = (x @ W1) * dinv, acc1 = 0.   x: [N,128], W1: [128,64]
__global__ __launch_bounds__(128) void gemm1_kernel(
    const float* __restrict__ X, const float* __restrict__ W, int nodes)
{
    __shared__ float Ws[128 * C1];
    for (int i = threadIdx.x; i < 128 * C1; i += 128) Ws[i] = W[i];
    __syncthreads();

    int row = blockIdx.x * 128 + threadIdx.x;
    if (row >= nodes) return;

    float acc[C1];
    #pragma unroll
    for (int j = 0; j < C1; j++) acc[j] = 0.0f;

    const float4* xr = reinterpret_cast<const float4*>(X) + (size_t)row * 32;
    #pragma unroll 2
    for (int k4 = 0; k4 < 32; k4++) {
        float4 xv = xr[k4];
        const float* wr = &Ws[k4 * 4 * C1];
        #pragma unroll
        for (int j = 0; j < C1; j++) acc[j] = fmaf(xv.x, wr[j], acc[j]);
        #pragma unroll
        for (int j = 0; j < C1; j++) acc[j] = fmaf(xv.y, wr[C1 + j], acc[j]);
        #pragma unroll
        for (int j = 0; j < C1; j++) acc[j] = fmaf(xv.z, wr[2 * C1 + j], acc[j]);
        #pragma unroll
        for (int j = 0; j < C1; j++) acc[j] = fmaf(xv.w, wr[3 * C1 + j], acc[j]);
    }

    float d = g_dinv[row];
    float4* gp = reinterpret_cast<float4*>(g_g1) + (size_t)row * (C1 / 4);
    float4* ap = reinterpret_cast<float4*>(g_acc1) + (size_t)row * (C1 / 4);
    #pragma unroll
    for (int j4 = 0; j4 < C1 / 4; j4++) {
        float4 o;
        o.x = acc[j4 * 4 + 0] * d;
        o.y = acc[j4 * 4 + 1] * d;
        o.z = acc[j4 * 4 + 2] * d;
        o.w = acc[j4 * 4 + 3] * d;
        gp[j4] = o;
        ap[j4] = make_float4(0.f, 0.f, 0.f, 0.f);
    }
}

// ---------------------------------------------------------------------------
// Scatter layer 1: acc1[dst] += g1[src]  (64 ch = 16 float4 per edge)
__global__ void scatter1_kernel(const void* __restrict__ ei, int E) {
    int t = blockIdx.x * blockDim.x + threadIdx.x;
    int e = t >> 4;
    if (e >= E) return;
    int c4 = t & 15;
    int is64 = g_is64;
    int src = load_idx(ei, is64, e);
    int dst = load_idx(ei, is64, (long long)E + e);
    float4 v = reinterpret_cast<const float4*>(g_g1)[src * 16 + c4];
    float4* a = reinterpret_cast<float4*>(g_acc1) + (dst * 16 + c4);
    asm volatile("red.global.add.v4.f32 [%0], {%1,%2,%3,%4};"
                 :: "l"(a), "f"(v.x), "f"(v.y), "f"(v.z), "f"(v.w) : "memory");
}

// ---------------------------------------------------------------------------
// Fused pointwise1 + GEMM2:
//   h = relu(dinv*(acc1+g1) + b1);  g2 = (h @ W2) * dinv;  acc2 = 0
//   W2: [64,32]
__global__ __launch_bounds__(128) void gemm2_kernel(
    const float* __restrict__ b1, const float* __restrict__ W2, int nodes)
{
    __shared__ float Ws[C1 * C2];
    __shared__ float bs[C1];
    for (int i = threadIdx.x; i < C1 * C2; i += 128) Ws[i] = W2[i];
    if (threadIdx.x < C1) bs[threadIdx.x] = b1[threadIdx.x];
    __syncthreads();

    int row = blockIdx.x * 128 + threadIdx.x;
    if (row >= nodes) return;

    float d = g_dinv[row];
    float acc[C2];
    #pragma unroll
    for (int j = 0; j < C2; j++) acc[j] = 0.0f;

    const float4* ar = reinterpret_cast<const float4*>(g_acc1) + (size_t)row * (C1 / 4);
    const float4* gr = reinterpret_cast<const float4*>(g_g1) + (size_t)row * (C1 / 4);

    #pragma unroll 2
    for (int k4 = 0; k4 < C1 / 4; k4++) {
        float4 a = ar[k4];
        float4 g = gr[k4];
        float h0 = fmaxf(fmaf(d, a.x + g.x, bs[k4 * 4 + 0]), 0.0f);
        float h1 = fmaxf(fmaf(d, a.y + g.y, bs[k4 * 4 + 1]), 0.0f);
        float h2 = fmaxf(fmaf(d, a.z + g.z, bs[k4 * 4 + 2]), 0.0f);
        float h3 = fmaxf(fmaf(d, a.w + g.w, bs[k4 * 4 + 3]), 0.0f);
        const float* wr = &Ws[k4 * 4 * C2];
        #pragma unroll
        for (int j = 0; j < C2; j++) acc[j] = fmaf(h0, wr[j], acc[j]);
        #pragma unroll
        for (int j = 0; j < C2; j++) acc[j] = fmaf(h1, wr[C2 + j], acc[j]);
        #pragma unroll
        for (int j = 0; j < C2; j++) acc[j] = fmaf(h2, wr[2 * C2 + j], acc[j]);
        #pragma unroll
        for (int j = 0; j < C2; j++) acc[j] = fmaf(h3, wr[3 * C2 + j], acc[j]);
    }

    float4* gp = reinterpret_cast<float4*>(g_g2) + (size_t)row * (C2 / 4);
    float4* ap = reinterpret_cast<float4*>(g_acc2) + (size_t)row * (C2 / 4);
    #pragma unroll
    for (int j4 = 0; j4 < C2 / 4; j4++) {
        float4 o;
        o.x = acc[j4 * 4 + 0] * d;
        o.y = acc[j4 * 4 + 1] * d;
        o.z = acc[j4 * 4 + 2] * d;
        o.w = acc[j4 * 4 + 3] * d;
        gp[j4] = o;
        ap[j4] = make_float4(0.f, 0.f, 0.f, 0.f);
    }
}

// ---------------------------------------------------------------------------
// Scatter layer 2: acc2[dst] += g2[src]  (32 ch = 8 float4 per edge)
__global__ void scatter2_kernel(const void* __restrict__ ei, int E) {
    int t = blockIdx.x * blockDim.x + threadIdx.x;
    int e = t >> 3;
    if (e >= E) return;
    int c4 = t & 7;
    int is64 = g_is64;
    int src = load_idx(ei, is64, e);
    int dst = load_idx(ei, is64, (long long)E + e);
    float4 v = reinterpret_cast<const float4*>(g_g2)[src * 8 + c4];
    float4* a = reinterpret_cast<float4*>(g_acc2) + (dst * 8 + c4);
    asm volatile("red.global.add.v4.f32 [%0], {%1,%2,%3,%4};"
                 :: "l"(a), "f"(v.x), "f"(v.y), "f"(v.z), "f"(v.w) : "memory");
}

// ---------------------------------------------------------------------------
// Final: h2 = relu(dinv*(acc2+g2)+b2); out = h2 @ Wh + bh  (warp per row)
__global__ void final_kernel(const float* __restrict__ b2,
                             const float* __restrict__ Wh,
                             const float* __restrict__ bh,
                             float* __restrict__ out, int nodes)
{
    int gtid = blockIdx.x * blockDim.x + threadIdx.x;
    int row = gtid >> 5;
    int lane = gtid & 31;
    if (row >= nodes) return;
    float d = g_dinv[row];
    float a = g_acc2[row * C2 + lane];
    float g = g_g2[row * C2 + lane];
    float v = fmaxf(fmaf(d, a + g, b2[lane]), 0.0f);
    float p = v * Wh[lane];
    #pragma unroll
    for (int o = 16; o > 0; o >>= 1) p += __shfl_xor_sync(0xffffffffu, p, o);
    if (lane == 0) out[row] = p + bh[0];
}

// ---------------------------------------------------------------------------
extern "C" void kernel_launch(void* const* d_in, const int* in_sizes, int n_in,
                              void* d_out, int out_size)
{
    const float* x  = (const float*)d_in[0];
    const void*  ei = d_in[1];
    const float* W1 = (const float*)d_in[2];
    const float* b1 = (const float*)d_in[3];
    const float* W2 = (const float*)d_in[4];
    const float* b2 = (const float*)d_in[5];
    const float* Wh = (const float*)d_in[6];
    const float* bh = (const float*)d_in[7];
    float* out = (float*)d_out;

    int nodes = in_sizes[0] / 128;
    int E = in_sizes[1] / 2;

    detect_kernel<<<1, 32>>>(ei);

    deg_init_kernel<<<(nodes + 255) / 256, 256>>>(nodes);
    deg_count_kernel<<<(E + 255) / 256, 256>>>(ei, E);
    deg_inv_kernel<<<(nodes + 255) / 256, 256>>>(nodes);

    gemm1_kernel<<<(nodes + 127) / 128, 128>>>(x, W1, nodes);

    {
        long long total = (long long)E * 16;
        int blocks = (int)((total + 255) / 256);
        scatter1_kernel<<<blocks, 256>>>(ei, E);
    }

    gemm2_kernel<<<(nodes + 127) / 128, 128>>>(b1, W2, nodes);

    {
        long long total = (long long)E * 8;
        int blocks = (int)((total + 255) / 256);
        scatter2_kernel<<<blocks, 256>>>(ei, E);
    }

    final_kernel<<<(nodes * 32 + 255) / 256, 256>>>(b2, Wh, bh, out, nodes);
}

// round 2
// speedup vs baseline: 1.2322x; 1.2322x over previous
#include <cuda_runtime.h>
#include <cuda_bf16.h>
#include <cstdint>

// Problem constants: 50000 nodes, 1.6M edges, 128->64->32->1
#define MAXN 50000
#define MAXE 1600000
#define C1 64
#define C2 32

// Scratch (static __device__ — no allocation allowed)
__device__ float g_dinv[MAXN];
__device__ int   g_deg[MAXN];
__device__ int   g_rowptr[MAXN];
__device__ int   g_cursor[MAXN];
__device__ int   g_srcs[MAXE];
__device__ int   g_blocksum[256];
__device__ int   g_blockoff[256];
__device__ float g_g1[(size_t)MAXN * C1];
__device__ float g_acc1[(size_t)MAXN * C1];
__device__ float g_g2[(size_t)MAXN * C2];
__device__ float g_acc2[(size_t)MAXN * C2];
__device__ int   g_is64;

// ---------------------------------------------------------------------------
// edge_index dtype detection (int64 per reference, int32 if jax x64 disabled).
__global__ void detect_kernel(const void* __restrict__ ei) {
    if (blockIdx.x == 0 && threadIdx.x == 0) {
        const unsigned int* p = (const unsigned int*)ei;
        int is64 = 1;
        #pragma unroll
        for (int i = 0; i < 32; i++) {
            if (p[2 * i + 1] != 0u) { is64 = 0; break; }
        }
        g_is64 = is64;
    }
}

__device__ __forceinline__ int load_idx(const void* ei, int is64, long long pos) {
    if (is64) return (int)((const long long*)ei)[pos];
    return ((const int*)ei)[pos];
}

// ---------------------------------------------------------------------------
// Degree histogram
__global__ void deg_zero_kernel(int nodes) {
    int i = blockIdx.x * blockDim.x + threadIdx.x;
    if (i < nodes) g_deg[i] = 0;
}

__global__ void deg_count_kernel(const void* __restrict__ ei, int E) {
    int e = blockIdx.x * blockDim.x + threadIdx.x;
    if (e >= E) return;
    int dst = load_idx(ei, g_is64, (long long)E + e);
    atomicAdd(&g_deg[dst], 1);
}

// ---------------------------------------------------------------------------
// Exclusive prefix scan over degrees -> rowptr (3 small kernels)
__global__ void scan_block_kernel(int nodes) {
    __shared__ int s[256];
    int i = blockIdx.x * 256 + threadIdx.x;
    int v = (i < nodes) ? g_deg[i] : 0;
    s[threadIdx.x] = v;
    __syncthreads();
    #pragma unroll
    for (int o = 1; o < 256; o <<= 1) {
        int t = (threadIdx.x >= o) ? s[threadIdx.x - o] : 0;
        __syncthreads();
        s[threadIdx.x] += t;
        __syncthreads();
    }
    if (i < nodes) g_rowptr[i] = s[threadIdx.x] - v;   // exclusive
    if (threadIdx.x == 255) g_blocksum[blockIdx.x] = s[255];
}

__global__ void scan_top_kernel(int nblocks) {
    __shared__ int s[256];
    int v = (threadIdx.x < nblocks) ? g_blocksum[threadIdx.x] : 0;
    s[threadIdx.x] = v;
    __syncthreads();
    #pragma unroll
    for (int o = 1; o < 256; o <<= 1) {
        int t = (threadIdx.x >= o) ? s[threadIdx.x - o] : 0;
        __syncthreads();
        s[threadIdx.x] += t;
        __syncthreads();
    }
    if (threadIdx.x < nblocks) g_blockoff[threadIdx.x] = s[threadIdx.x] - v;
}

__global__ void scan_add_kernel(int nodes) {
    int i = blockIdx.x * blockDim.x + threadIdx.x;
    if (i >= nodes) return;
    int r = g_rowptr[i] + g_blockoff[i >> 8];
    g_rowptr[i] = r;
    g_cursor[i] = r;
    g_dinv[i] = rsqrtf((float)g_deg[i] + 1.0f);
}

// ---------------------------------------------------------------------------
// Counting-sort edges by dst: g_srcs holds src ids grouped by dst
__global__ void sort_kernel(const void* __restrict__ ei, int E) {
    int e = blockIdx.x * blockDim.x + threadIdx.x;
    if (e >= E) return;
    int is64 = g_is64;
    int src = load_idx(ei, is64, e);
    int dst = load_idx(ei, is64, (long long)E + e);
    int pos = atomicAdd(&g_cursor[dst], 1);
    g_srcs[pos] = src;
}

// ---------------------------------------------------------------------------
// GEMM1: g1 = (x @ W1) * dinv.   x: [N,128], W1: [128,64]
__global__ __launch_bounds__(128) void gemm1_kernel(
    const float* __restrict__ X, const float* __restrict__ W, int nodes)
{
    __shared__ float Ws[128 * C1];
    for (int i = threadIdx.x; i < 128 * C1; i += 128) Ws[i] = W[i];
    __syncthreads();

    int row = blockIdx.x * 128 + threadIdx.x;
    if (row >= nodes) return;

    float acc[C1];
    #pragma unroll
    for (int j = 0; j < C1; j++) acc[j] = 0.0f;

    const float4* xr = reinterpret_cast<const float4*>(X) + (size_t)row * 32;
    #pragma unroll 2
    for (int k4 = 0; k4 < 32; k4++) {
        float4 xv = xr[k4];
        const float* wr = &Ws[k4 * 4 * C1];
        #pragma unroll
        for (int j = 0; j < C1; j++) acc[j] = fmaf(xv.x, wr[j], acc[j]);
        #pragma unroll
        for (int j = 0; j < C1; j++) acc[j] = fmaf(xv.y, wr[C1 + j], acc[j]);
        #pragma unroll
        for (int j = 0; j < C1; j++) acc[j] = fmaf(xv.z, wr[2 * C1 + j], acc[j]);
        #pragma unroll
        for (int j = 0; j < C1; j++) acc[j] = fmaf(xv.w, wr[3 * C1 + j], acc[j]);
    }

    float d = g_dinv[row];
    float4* gp = reinterpret_cast<float4*>(g_g1) + (size_t)row * (C1 / 4);
    #pragma unroll
    for (int j4 = 0; j4 < C1 / 4; j4++) {
        float4 o;
        o.x = acc[j4 * 4 + 0] * d;
        o.y = acc[j4 * 4 + 1] * d;
        o.z = acc[j4 * 4 + 2] * d;
        o.w = acc[j4 * 4 + 3] * d;
        gp[j4] = o;
    }
}

// ---------------------------------------------------------------------------
// Gather layer 1: acc1[n] = sum over CSR segment of g1[src].
// 16 threads per node, one float4 channel-slice each. 2-way unrolled for MLP.
__global__ void gather1_kernel(int nodes) {
    int t = blockIdx.x * blockDim.x + threadIdx.x;
    int node = t >> 4;
    if (node >= nodes) return;
    int c4 = t & 15;
    int deg = g_deg[node];
    int base = g_rowptr[node];
    const float4* G = reinterpret_cast<const float4*>(g_g1);

    float4 a0 = make_float4(0.f, 0.f, 0.f, 0.f);
    float4 a1 = make_float4(0.f, 0.f, 0.f, 0.f);
    int i = 0;
    for (; i + 2 <= deg; i += 2) {
        int s0 = g_srcs[base + i];
        int s1 = g_srcs[base + i + 1];
        float4 v0 = G[s0 * 16 + c4];
        float4 v1 = G[s1 * 16 + c4];
        a0.x += v0.x; a0.y += v0.y; a0.z += v0.z; a0.w += v0.w;
        a1.x += v1.x; a1.y += v1.y; a1.z += v1.z; a1.w += v1.w;
    }
    if (i < deg) {
        int s = g_srcs[base + i];
        float4 v = G[s * 16 + c4];
        a0.x += v.x; a0.y += v.y; a0.z += v.z; a0.w += v.w;
    }
    float4 r;
    r.x = a0.x + a1.x; r.y = a0.y + a1.y;
    r.z = a0.z + a1.z; r.w = a0.w + a1.w;
    reinterpret_cast<float4*>(g_acc1)[node * 16 + c4] = r;
}

// ---------------------------------------------------------------------------
// Fused pointwise1 + GEMM2: h = relu(dinv*(acc1+g1)+b1); g2 = (h @ W2)*dinv
__global__ __launch_bounds__(128) void gemm2_kernel(
    const float* __restrict__ b1, const float* __restrict__ W2, int nodes)
{
    __shared__ float Ws[C1 * C2];
    __shared__ float bs[C1];
    for (int i = threadIdx.x; i < C1 * C2; i += 128) Ws[i] = W2[i];
    if (threadIdx.x < C1) bs[threadIdx.x] = b1[threadIdx.x];
    __syncthreads();

    int row = blockIdx.x * 128 + threadIdx.x;
    if (row >= nodes) return;

    float d = g_dinv[row];
    float acc[C2];
    #pragma unroll
    for (int j = 0; j < C2; j++) acc[j] = 0.0f;

    const float4* ar = reinterpret_cast<const float4*>(g_acc1) + (size_t)row * (C1 / 4);
    const float4* gr = reinterpret_cast<const float4*>(g_g1) + (size_t)row * (C1 / 4);

    #pragma unroll 2
    for (int k4 = 0; k4 < C1 / 4; k4++) {
        float4 a = ar[k4];
        float4 g = gr[k4];
        float h0 = fmaxf(fmaf(d, a.x + g.x, bs[k4 * 4 + 0]), 0.0f);
        float h1 = fmaxf(fmaf(d, a.y + g.y, bs[k4 * 4 + 1]), 0.0f);
        float h2 = fmaxf(fmaf(d, a.z + g.z, bs[k4 * 4 + 2]), 0.0f);
        float h3 = fmaxf(fmaf(d, a.w + g.w, bs[k4 * 4 + 3]), 0.0f);
        const float* wr = &Ws[k4 * 4 * C2];
        #pragma unroll
        for (int j = 0; j < C2; j++) acc[j] = fmaf(h0, wr[j], acc[j]);
        #pragma unroll
        for (int j = 0; j < C2; j++) acc[j] = fmaf(h1, wr[C2 + j], acc[j]);
        #pragma unroll
        for (int j = 0; j < C2; j++) acc[j] = fmaf(h2, wr[2 * C2 + j], acc[j]);
        #pragma unroll
        for (int j = 0; j < C2; j++) acc[j] = fmaf(h3, wr[3 * C2 + j], acc[j]);
    }

    float4* gp = reinterpret_cast<float4*>(g_g2) + (size_t)row * (C2 / 4);
    #pragma unroll
    for (int j4 = 0; j4 < C2 / 4; j4++) {
        float4 o;
        o.x = acc[j4 * 4 + 0] * d;
        o.y = acc[j4 * 4 + 1] * d;
        o.z = acc[j4 * 4 + 2] * d;
        o.w = acc[j4 * 4 + 3] * d;
        gp[j4] = o;
    }
}

// ---------------------------------------------------------------------------
// Gather layer 2: acc2[n] = sum of g2[src]. 8 threads per node.
__global__ void gather2_kernel(int nodes) {
    int t = blockIdx.x * blockDim.x + threadIdx.x;
    int node = t >> 3;
    if (node >= nodes) return;
    int c4 = t & 7;
    int deg = g_deg[node];
    int base = g_rowptr[node];
    const float4* G = reinterpret_cast<const float4*>(g_g2);

    float4 a0 = make_float4(0.f, 0.f, 0.f, 0.f);
    float4 a1 = make_float4(0.f, 0.f, 0.f, 0.f);
    int i = 0;
    for (; i + 2 <= deg; i += 2) {
        int s0 = g_srcs[base + i];
        int s1 = g_srcs[base + i + 1];
        float4 v0 = G[s0 * 8 + c4];
        float4 v1 = G[s1 * 8 + c4];
        a0.x += v0.x; a0.y += v0.y; a0.z += v0.z; a0.w += v0.w;
        a1.x += v1.x; a1.y += v1.y; a1.z += v1.z; a1.w += v1.w;
    }
    if (i < deg) {
        int s = g_srcs[base + i];
        float4 v = G[s * 8 + c4];
        a0.x += v.x; a0.y += v.y; a0.z += v.z; a0.w += v.w;
    }
    float4 r;
    r.x = a0.x + a1.x; r.y = a0.y + a1.y;
    r.z = a0.z + a1.z; r.w = a0.w + a1.w;
    reinterpret_cast<float4*>(g_acc2)[node * 8 + c4] = r;
}

// ---------------------------------------------------------------------------
// Final: h2 = relu(dinv*(acc2+g2)+b2); out = h2 @ Wh + bh  (warp per row)
__global__ void final_kernel(const float* __restrict__ b2,
                             const float* __restrict__ Wh,
                             const float* __restrict__ bh,
                             float* __restrict__ out, int nodes)
{
    int gtid = blockIdx.x * blockDim.x + threadIdx.x;
    int row = gtid >> 5;
    int lane = gtid & 31;
    if (row >= nodes) return;
    float d = g_dinv[row];
    float a = g_acc2[row * C2 + lane];
    float g = g_g2[row * C2 + lane];
    float v = fmaxf(fmaf(d, a + g, b2[lane]), 0.0f);
    float p = v * Wh[lane];
    #pragma unroll
    for (int o = 16; o > 0; o >>= 1) p += __shfl_xor_sync(0xffffffffu, p, o);
    if (lane == 0) out[row] = p + bh[0];
}

// ---------------------------------------------------------------------------
extern "C" void kernel_launch(void* const* d_in, const int* in_sizes, int n_in,
                              void* d_out, int out_size)
{
    const float* x  = (const float*)d_in[0];
    const void*  ei = d_in[1];
    const float* W1 = (const float*)d_in[2];
    const float* b1 = (const float*)d_in[3];
    const float* W2 = (const float*)d_in[4];
    const float* b2 = (const float*)d_in[5];
    const float* Wh = (const float*)d_in[6];
    const float* bh = (const float*)d_in[7];
    float* out = (float*)d_out;

    int nodes = in_sizes[0] / 128;
    int E = in_sizes[1] / 2;
    int nblocks = (nodes + 255) / 256;

    detect_kernel<<<1, 32>>>(ei);

    deg_zero_kernel<<<nblocks, 256>>>(nodes);
    deg_count_kernel<<<(E + 255) / 256, 256>>>(ei, E);

    scan_block_kernel<<<nblocks, 256>>>(nodes);
    scan_top_kernel<<<1, 256>>>(nblocks);
    scan_add_kernel<<<nblocks, 256>>>(nodes);

    sort_kernel<<<(E + 255) / 256, 256>>>(ei, E);

    gemm1_kernel<<<(nodes + 127) / 128, 128>>>(x, W1, nodes);
    gather1_kernel<<<(nodes * 16 + 255) / 256, 256>>>(nodes);
    gemm2_kernel<<<(nodes + 127) / 128, 128>>>(b1, W2, nodes);
    gather2_kernel<<<(nodes * 8 + 255) / 256, 256>>>(nodes);
    final_kernel<<<(nodes * 32 + 255) / 256, 256>>>(b2, Wh, bh, out, nodes);
}

// round 3
// speedup vs baseline: 1.2492x; 1.0138x over previous
#include <cuda_runtime.h>
#include <cuda_fp16.h>
#include <cstdint>

// Problem constants: 50000 nodes, 1.6M edges, 128->64->32->1
#define MAXN 50000
#define MAXE 1600000
#define C1 64
#define C2 32

// Scratch (static __device__ — no allocation allowed)
__device__ float g_dinv[MAXN];
__device__ int   g_deg[MAXN];
__device__ int   g_rowptr[MAXN];
__device__ int   g_cursor[MAXN];
__device__ int   g_srcs[MAXE];
__device__ int   g_blocksum[256];
__device__ __align__(16) __half g_g1h[(size_t)MAXN * C1];
__device__ __align__(16) float  g_acc1[(size_t)MAXN * C1];
__device__ __align__(16) __half g_g2h[(size_t)MAXN * C2];
__device__ __align__(16) float  g_acc2[(size_t)MAXN * C2];
__device__ int   g_is64;

__device__ __forceinline__ int load_idx(const void* ei, int is64, long long pos) {
    if (is64) return (int)((const long long*)ei)[pos];
    return ((const int*)ei)[pos];
}

// ---------------------------------------------------------------------------
// init: zero degree counters + edge dtype sniff (int64 vs int32)
__global__ void init_kernel(const void* __restrict__ ei, int nodes) {
    int i = blockIdx.x * blockDim.x + threadIdx.x;
    if (i < nodes) g_deg[i] = 0;
    if (blockIdx.x == 0 && threadIdx.x == 0) {
        const unsigned int* p = (const unsigned int*)ei;
        int is64 = 1;
        #pragma unroll
        for (int k = 0; k < 32; k++) {
            if (p[2 * k + 1] != 0u) { is64 = 0; break; }
        }
        g_is64 = is64;
    }
}

// ---------------------------------------------------------------------------
// Fused: degree histogram (blocks [0, degBlocks)) + GEMM1 (remaining blocks).
// GEMM1: g1h = fp16(x @ W1)   (UNscaled — dinv folded in at gather time)
__global__ __launch_bounds__(256) void deg_gemm1_kernel(
    const void* __restrict__ ei, int E,
    const float* __restrict__ X, const float* __restrict__ W,
    int nodes, int degBlocks)
{
    __shared__ float Ws[128 * C1];

    if ((int)blockIdx.x < degBlocks) {
        int e = blockIdx.x * 256 + threadIdx.x;
        if (e < E) {
            int dst = load_idx(ei, g_is64, (long long)E + e);
            atomicAdd(&g_deg[dst], 1);
        }
        return;
    }

    for (int i = threadIdx.x; i < 128 * C1; i += 256) Ws[i] = W[i];
    __syncthreads();

    int row = (blockIdx.x - degBlocks) * 256 + threadIdx.x;
    if (row >= nodes) return;

    float acc[C1];
    #pragma unroll
    for (int j = 0; j < C1; j++) acc[j] = 0.0f;

    const float4* xr = reinterpret_cast<const float4*>(X) + (size_t)row * 32;
    #pragma unroll 2
    for (int k4 = 0; k4 < 32; k4++) {
        float4 xv = xr[k4];
        const float* wr = &Ws[k4 * 4 * C1];
        #pragma unroll
        for (int j = 0; j < C1; j++) acc[j] = fmaf(xv.x, wr[j], acc[j]);
        #pragma unroll
        for (int j = 0; j < C1; j++) acc[j] = fmaf(xv.y, wr[C1 + j], acc[j]);
        #pragma unroll
        for (int j = 0; j < C1; j++) acc[j] = fmaf(xv.z, wr[2 * C1 + j], acc[j]);
        #pragma unroll
        for (int j = 0; j < C1; j++) acc[j] = fmaf(xv.w, wr[3 * C1 + j], acc[j]);
    }

    // store fp16 row (64 halves = 8 uint4)
    uint4* gp = reinterpret_cast<uint4*>(g_g1h) + (size_t)row * 8;
    #pragma unroll
    for (int j = 0; j < 8; j++) {
        __half2 h0 = __floats2half2_rn(acc[j * 8 + 0], acc[j * 8 + 1]);
        __half2 h1 = __floats2half2_rn(acc[j * 8 + 2], acc[j * 8 + 3]);
        __half2 h2 = __floats2half2_rn(acc[j * 8 + 4], acc[j * 8 + 5]);
        __half2 h3 = __floats2half2_rn(acc[j * 8 + 6], acc[j * 8 + 7]);
        uint4 o;
        o.x = *reinterpret_cast<unsigned int*>(&h0);
        o.y = *reinterpret_cast<unsigned int*>(&h1);
        o.z = *reinterpret_cast<unsigned int*>(&h2);
        o.w = *reinterpret_cast<unsigned int*>(&h3);
        gp[j] = o;
    }
}

// ---------------------------------------------------------------------------
// Scan pass 1: per-block inclusive scan of degrees -> exclusive rowptr + blocksums
__global__ void scan_block_kernel(int nodes) {
    __shared__ int s[256];
    int i = blockIdx.x * 256 + threadIdx.x;
    int v = (i < nodes) ? g_deg[i] : 0;
    s[threadIdx.x] = v;
    __syncthreads();
    #pragma unroll
    for (int o = 1; o < 256; o <<= 1) {
        int t = (threadIdx.x >= o) ? s[threadIdx.x - o] : 0;
        __syncthreads();
        s[threadIdx.x] += t;
        __syncthreads();
    }
    if (i < nodes) g_rowptr[i] = s[threadIdx.x] - v;   // exclusive within block
    if (threadIdx.x == 255) g_blocksum[blockIdx.x] = s[255];
}

// Scan pass 2: every block redundantly scans the block sums (<=256 of them),
// adds its offset, finalizes rowptr/cursor/dinv.
__global__ void scan_finish_kernel(int nodes, int nblocks) {
    __shared__ int s[256];
    int v = (threadIdx.x < nblocks) ? g_blocksum[threadIdx.x] : 0;
    s[threadIdx.x] = v;
    __syncthreads();
    #pragma unroll
    for (int o = 1; o < 256; o <<= 1) {
        int t = (threadIdx.x >= o) ? s[threadIdx.x - o] : 0;
        __syncthreads();
        s[threadIdx.x] += t;
        __syncthreads();
    }
    int i = blockIdx.x * 256 + threadIdx.x;
    if (i < nodes) {
        int off = (blockIdx.x > 0) ? s[blockIdx.x - 1] : 0;
        int r = g_rowptr[i] + off;
        g_rowptr[i] = r;
        g_cursor[i] = r;
        g_dinv[i] = rsqrtf((float)g_deg[i] + 1.0f);
    }
}

// ---------------------------------------------------------------------------
// Counting-sort edges by dst
__global__ void sort_kernel(const void* __restrict__ ei, int E) {
    int e = blockIdx.x * blockDim.x + threadIdx.x;
    if (e >= E) return;
    int is64 = g_is64;
    int src = load_idx(ei, is64, e);
    int dst = load_idx(ei, is64, (long long)E + e);
    int pos = atomicAdd(&g_cursor[dst], 1);
    g_srcs[pos] = src;
}

// ---------------------------------------------------------------------------
__device__ __forceinline__ void acc_h8(float* acc, uint4 v, float d) {
    __half2 p0 = *reinterpret_cast<__half2*>(&v.x);
    __half2 p1 = *reinterpret_cast<__half2*>(&v.y);
    __half2 p2 = *reinterpret_cast<__half2*>(&v.z);
    __half2 p3 = *reinterpret_cast<__half2*>(&v.w);
    float2 f0 = __half22float2(p0);
    float2 f1 = __half22float2(p1);
    float2 f2 = __half22float2(p2);
    float2 f3 = __half22float2(p3);
    acc[0] = fmaf(d, f0.x, acc[0]); acc[1] = fmaf(d, f0.y, acc[1]);
    acc[2] = fmaf(d, f1.x, acc[2]); acc[3] = fmaf(d, f1.y, acc[3]);
    acc[4] = fmaf(d, f2.x, acc[4]); acc[5] = fmaf(d, f2.y, acc[5]);
    acc[6] = fmaf(d, f3.x, acc[6]); acc[7] = fmaf(d, f3.y, acc[7]);
}

// Gather layer 1: acc1[n] = sum_{s in N(n)} dinv[s] * g1h[s].
// 8 lanes per node; each lane owns 8 channels (one uint4 of halves).
__global__ void gather1_kernel(int nodes) {
    int t = blockIdx.x * blockDim.x + threadIdx.x;
    int node = t >> 3;
    if (node >= nodes) return;
    int c = t & 7;
    int deg = g_deg[node];
    int base = g_rowptr[node];
    const uint4* G = reinterpret_cast<const uint4*>(g_g1h);

    float acc[8];
    #pragma unroll
    for (int j = 0; j < 8; j++) acc[j] = 0.0f;

    int i = 0;
    for (; i + 4 <= deg; i += 4) {
        int s0 = g_srcs[base + i + 0];
        int s1 = g_srcs[base + i + 1];
        int s2 = g_srcs[base + i + 2];
        int s3 = g_srcs[base + i + 3];
        float d0 = g_dinv[s0], d1 = g_dinv[s1], d2 = g_dinv[s2], d3 = g_dinv[s3];
        uint4 v0 = G[s0 * 8 + c];
        uint4 v1 = G[s1 * 8 + c];
        uint4 v2 = G[s2 * 8 + c];
        uint4 v3 = G[s3 * 8 + c];
        acc_h8(acc, v0, d0);
        acc_h8(acc, v1, d1);
        acc_h8(acc, v2, d2);
        acc_h8(acc, v3, d3);
    }
    for (; i < deg; i++) {
        int s = g_srcs[base + i];
        acc_h8(acc, G[s * 8 + c], g_dinv[s]);
    }

    float4* ap = reinterpret_cast<float4*>(g_acc1) + (size_t)node * 16 + c * 2;
    ap[0] = make_float4(acc[0], acc[1], acc[2], acc[3]);
    ap[1] = make_float4(acc[4], acc[5], acc[6], acc[7]);
}

// ---------------------------------------------------------------------------
// Fused pointwise1 + GEMM2:
//   h = relu(dinv*(acc1 + dinv*g1) + b1);  g2h = fp16(h @ W2)  (unscaled)
__global__ __launch_bounds__(256) void gemm2_kernel(
    const float* __restrict__ b1, const float* __restrict__ W2, int nodes)
{
    __shared__ float Ws[C1 * C2];
    __shared__ float bs[C1];
    for (int i = threadIdx.x; i < C1 * C2; i += 256) Ws[i] = W2[i];
    if (threadIdx.x < C1) bs[threadIdx.x] = b1[threadIdx.x];
    __syncthreads();

    int row = blockIdx.x * 256 + threadIdx.x;
    if (row >= nodes) return;

    float d = g_dinv[row];
    float acc[C2];
    #pragma unroll
    for (int j = 0; j < C2; j++) acc[j] = 0.0f;

    const float2*  ar = reinterpret_cast<const float2*>(g_acc1) + (size_t)row * 32;
    const __half2* gr = reinterpret_cast<const __half2*>(g_g1h) + (size_t)row * 32;

    #pragma unroll 4
    for (int k2 = 0; k2 < 32; k2++) {
        float2 a = ar[k2];
        float2 g = __half22float2(gr[k2]);
        float h0 = fmaxf(fmaf(d, fmaf(d, g.x, a.x), bs[k2 * 2 + 0]), 0.0f);
        float h1 = fmaxf(fmaf(d, fmaf(d, g.y, a.y), bs[k2 * 2 + 1]), 0.0f);
        const float* wr = &Ws[k2 * 2 * C2];
        #pragma unroll
        for (int j = 0; j < C2; j++) acc[j] = fmaf(h0, wr[j], acc[j]);
        #pragma unroll
        for (int j = 0; j < C2; j++) acc[j] = fmaf(h1, wr[C2 + j], acc[j]);
    }

    uint4* gp = reinterpret_cast<uint4*>(g_g2h) + (size_t)row * 4;
    #pragma unroll
    for (int j = 0; j < 4; j++) {
        __half2 h0 = __floats2half2_rn(acc[j * 8 + 0], acc[j * 8 + 1]);
        __half2 h1 = __floats2half2_rn(acc[j * 8 + 2], acc[j * 8 + 3]);
        __half2 h2 = __floats2half2_rn(acc[j * 8 + 4], acc[j * 8 + 5]);
        __half2 h3 = __floats2half2_rn(acc[j * 8 + 6], acc[j * 8 + 7]);
        uint4 o;
        o.x = *reinterpret_cast<unsigned int*>(&h0);
        o.y = *reinterpret_cast<unsigned int*>(&h1);
        o.z = *reinterpret_cast<unsigned int*>(&h2);
        o.w = *reinterpret_cast<unsigned int*>(&h3);
        gp[j] = o;
    }
}

// ---------------------------------------------------------------------------
// Gather layer 2: 4 lanes per node, 8 channels each.
__global__ void gather2_kernel(int nodes) {
    int t = blockIdx.x * blockDim.x + threadIdx.x;
    int node = t >> 2;
    if (node >= nodes) return;
    int c = t & 3;
    int deg = g_deg[node];
    int base = g_rowptr[node];
    const uint4* G = reinterpret_cast<const uint4*>(g_g2h);

    float acc[8];
    #pragma unroll
    for (int j = 0; j < 8; j++) acc[j] = 0.0f;

    int i = 0;
    for (; i + 4 <= deg; i += 4) {
        int s0 = g_srcs[base + i + 0];
        int s1 = g_srcs[base + i + 1];
        int s2 = g_srcs[base + i + 2];
        int s3 = g_srcs[base + i + 3];
        float d0 = g_dinv[s0], d1 = g_dinv[s1], d2 = g_dinv[s2], d3 = g_dinv[s3];
        uint4 v0 = G[s0 * 4 + c];
        uint4 v1 = G[s1 * 4 + c];
        uint4 v2 = G[s2 * 4 + c];
        uint4 v3 = G[s3 * 4 + c];
        acc_h8(acc, v0, d0);
        acc_h8(acc, v1, d1);
        acc_h8(acc, v2, d2);
        acc_h8(acc, v3, d3);
    }
    for (; i < deg; i++) {
        int s = g_srcs[base + i];
        acc_h8(acc, G[s * 4 + c], g_dinv[s]);
    }

    float4* ap = reinterpret_cast<float4*>(g_acc2) + (size_t)node * 8 + c * 2;
    ap[0] = make_float4(acc[0], acc[1], acc[2], acc[3]);
    ap[1] = make_float4(acc[4], acc[5], acc[6], acc[7]);
}

// ---------------------------------------------------------------------------
// Final: h2 = relu(dinv*(acc2 + dinv*g2) + b2); out = h2 @ Wh + bh (warp/row)
__global__ void final_kernel(const float* __restrict__ b2,
                             const float* __restrict__ Wh,
                             const float* __restrict__ bh,
                             float* __restrict__ out, int nodes)
{
    int gtid = blockIdx.x * blockDim.x + threadIdx.x;
    int row = gtid >> 5;
    int lane = gtid & 31;
    if (row >= nodes) return;
    float d = g_dinv[row];
    float a = g_acc2[row * C2 + lane];
    float g = __half2float(g_g2h[row * C2 + lane]);
    float v = fmaxf(fmaf(d, fmaf(d, g, a), b2[lane]), 0.0f);
    float p = v * Wh[lane];
    #pragma unroll
    for (int o = 16; o > 0; o >>= 1) p += __shfl_xor_sync(0xffffffffu, p, o);
    if (lane == 0) out[row] = p + bh[0];
}

// ---------------------------------------------------------------------------
extern "C" void kernel_launch(void* const* d_in, const int* in_sizes, int n_in,
                              void* d_out, int out_size)
{
    const float* x  = (const float*)d_in[0];
    const void*  ei = d_in[1];
    const float* W1 = (const float*)d_in[2];
    const float* b1 = (const float*)d_in[3];
    const float* W2 = (const float*)d_in[4];
    const float* b2 = (const float*)d_in[5];
    const float* Wh = (const float*)d_in[6];
    const float* bh = (const float*)d_in[7];
    float* out = (float*)d_out;

    int nodes = in_sizes[0] / 128;
    int E = in_sizes[1] / 2;
    int nb = (nodes + 255) / 256;     // 196
    int degB = (E + 255) / 256;       // 6250

    init_kernel<<<nb, 256>>>(ei, nodes);
    deg_gemm1_kernel<<<degB + nb, 256>>>(ei, E, x, W1, nodes, degB);
    scan_block_kernel<<<nb, 256>>>(nodes);
    scan_finish_kernel<<<nb, 256>>>(nodes, nb);
    sort_kernel<<<degB, 256>>>(ei, E);
    gather1_kernel<<<(nodes * 8 + 255) / 256, 256>>>(nodes);
    gemm2_kernel<<<nb, 256>>>(b1, W2, nodes);
    gather2_kernel<<<(nodes * 4 + 255) / 256, 256>>>(nodes);
    final_kernel<<<(nodes * 32 + 255) / 256, 256>>>(b2, Wh, bh, out, nodes);
}

// round 4
// speedup vs baseline: 1.4662x; 1.1737x over previous
#include <cuda_runtime.h>
#include <cuda_fp16.h>
#include <mma.h>
#include <cstdint>

using namespace nvcuda;

// Problem constants: 50000 nodes, 1.6M edges, 128->64->32->1
#define MAXN 50000
#define MAXE 1600000
#define C1 64
#define C2 32

// Scratch (static __device__ — no allocation allowed)
__device__ float g_dinv[MAXN];
__device__ int   g_deg[MAXN];
__device__ int   g_rowptr[MAXN];
__device__ int   g_cursor[MAXN];
__device__ int   g_srcs[MAXE];
__device__ int   g_blocksum[256];
__device__ __align__(16) __half g_w1h[128 * C1];
__device__ __align__(16) __half g_g1h[(size_t)MAXN * C1];
__device__ __align__(16) __half g_g2h[(size_t)MAXN * C2];
__device__ int   g_is64;

__device__ __forceinline__ int load_idx(const void* ei, int is64, long long pos) {
    if (is64) return (int)((const long long*)ei)[pos];
    return ((const int*)ei)[pos];
}

// ---------------------------------------------------------------------------
// init: zero degree counters + dtype sniff + W1 -> fp16 conversion
__global__ void init_kernel(const void* __restrict__ ei,
                            const float* __restrict__ W1, int nodes) {
    int i = blockIdx.x * blockDim.x + threadIdx.x;
    if (i < nodes) g_deg[i] = 0;
    if (blockIdx.x == 0) {
        for (int k = threadIdx.x; k < 128 * C1; k += 256)
            g_w1h[k] = __float2half(W1[k]);
        if (threadIdx.x == 0) {
            const unsigned int* p = (const unsigned int*)ei;
            int is64 = 1;
            #pragma unroll
            for (int k = 0; k < 32; k++) {
                if (p[2 * k + 1] != 0u) { is64 = 0; break; }
            }
            g_is64 = is64;
        }
    }
}

// ---------------------------------------------------------------------------
// Fused: degree histogram (blocks [0, degBlocks)) + tensor-core GEMM1.
// GEMM1: g1h = fp16(x @ W1) (unscaled; dinv folded in at gather time).
// Block tile: 128 rows x 64 cols, 8 warps, each warp 16x64 via wmma.
__global__ __launch_bounds__(256) void deg_gemm1_kernel(
    const void* __restrict__ ei, int E,
    const float* __restrict__ X, int nodes, int degBlocks)
{
    __shared__ __align__(16) char buf[49152];

    if ((int)blockIdx.x < degBlocks) {
        int e = blockIdx.x * 256 + threadIdx.x;
        if (e < E) {
            int dst = load_idx(ei, g_is64, (long long)E + e);
            atomicAdd(&g_deg[dst], 1);
        }
        return;
    }

    __half* Xh  = reinterpret_cast<__half*>(buf);           // [128][128] 32KB
    __half* W1s = reinterpret_cast<__half*>(buf + 32768);   // [128][64]  16KB
    float*  Cs  = reinterpret_cast<float*>(buf);            // [128][64]  overlays Xh

    int tid = threadIdx.x;
    int rowBase = (blockIdx.x - degBlocks) * 128;

    // load X tile (fp32 -> fp16), zero-pad OOB rows
    #pragma unroll
    for (int i = 0; i < 16; i++) {
        int idx = tid + i * 256;          // float4 index within 128x32
        int row = idx >> 5;
        int k4  = idx & 31;
        float4 v = (rowBase + row < nodes)
            ? reinterpret_cast<const float4*>(X)[(size_t)(rowBase + row) * 32 + k4]
            : make_float4(0.f, 0.f, 0.f, 0.f);
        __half2 h0 = __floats2half2_rn(v.x, v.y);
        __half2 h1 = __floats2half2_rn(v.z, v.w);
        uint2 o;
        o.x = *reinterpret_cast<unsigned int*>(&h0);
        o.y = *reinterpret_cast<unsigned int*>(&h1);
        *reinterpret_cast<uint2*>(&Xh[row * 128 + k4 * 4]) = o;
    }
    // load W1 fp16 (8192 halves = 1024 uint4)
    #pragma unroll
    for (int i = 0; i < 4; i++) {
        int u = tid + i * 256;
        reinterpret_cast<uint4*>(W1s)[u] =
            reinterpret_cast<const uint4*>(g_w1h)[u];
    }
    __syncthreads();

    int warp = tid >> 5;
    wmma::fragment<wmma::accumulator, 16, 16, 16, float> c[4];
    #pragma unroll
    for (int n = 0; n < 4; n++) wmma::fill_fragment(c[n], 0.0f);

    #pragma unroll
    for (int k0 = 0; k0 < 8; k0++) {
        wmma::fragment<wmma::matrix_a, 16, 16, 16, __half, wmma::row_major> a;
        wmma::load_matrix_sync(a, Xh + warp * 16 * 128 + k0 * 16, 128);
        #pragma unroll
        for (int n = 0; n < 4; n++) {
            wmma::fragment<wmma::matrix_b, 16, 16, 16, __half, wmma::row_major> b;
            wmma::load_matrix_sync(b, W1s + k0 * 16 * 64 + n * 16, 64);
            wmma::mma_sync(c[n], a, b, c[n]);
        }
    }
    __syncthreads();   // done reading Xh; overlay with C stage
    #pragma unroll
    for (int n = 0; n < 4; n++)
        wmma::store_matrix_sync(Cs + warp * 16 * 64 + n * 16, c[n], 64,
                                wmma::mem_row_major);
    __syncthreads();

    // write g1h fp16 rows (128 rows x 8 uint4)
    #pragma unroll
    for (int i = 0; i < 4; i++) {
        int u = tid * 4 + i;
        int row = u >> 3;
        int c4  = u & 7;
        if (rowBase + row >= nodes) continue;
        const float* src = &Cs[row * 64 + c4 * 8];
        __half2 h0 = __floats2half2_rn(src[0], src[1]);
        __half2 h1 = __floats2half2_rn(src[2], src[3]);
        __half2 h2 = __floats2half2_rn(src[4], src[5]);
        __half2 h3 = __floats2half2_rn(src[6], src[7]);
        uint4 o;
        o.x = *reinterpret_cast<unsigned int*>(&h0);
        o.y = *reinterpret_cast<unsigned int*>(&h1);
        o.z = *reinterpret_cast<unsigned int*>(&h2);
        o.w = *reinterpret_cast<unsigned int*>(&h3);
        reinterpret_cast<uint4*>(g_g1h)[(size_t)(rowBase + row) * 8 + c4] = o;
    }
}

// ---------------------------------------------------------------------------
// Scan pass 1
__global__ void scan_block_kernel(int nodes) {
    __shared__ int s[256];
    int i = blockIdx.x * 256 + threadIdx.x;
    int v = (i < nodes) ? g_deg[i] : 0;
    s[threadIdx.x] = v;
    __syncthreads();
    #pragma unroll
    for (int o = 1; o < 256; o <<= 1) {
        int t = (threadIdx.x >= o) ? s[threadIdx.x - o] : 0;
        __syncthreads();
        s[threadIdx.x] += t;
        __syncthreads();
    }
    if (i < nodes) g_rowptr[i] = s[threadIdx.x] - v;
    if (threadIdx.x == 255) g_blocksum[blockIdx.x] = s[255];
}

// Scan pass 2 (redundant top scan per block) + dinv
__global__ void scan_finish_kernel(int nodes, int nblocks) {
    __shared__ int s[256];
    int v = (threadIdx.x < nblocks) ? g_blocksum[threadIdx.x] : 0;
    s[threadIdx.x] = v;
    __syncthreads();
    #pragma unroll
    for (int o = 1; o < 256; o <<= 1) {
        int t = (threadIdx.x >= o) ? s[threadIdx.x - o] : 0;
        __syncthreads();
        s[threadIdx.x] += t;
        __syncthreads();
    }
    int i = blockIdx.x * 256 + threadIdx.x;
    if (i < nodes) {
        int off = (blockIdx.x > 0) ? s[blockIdx.x - 1] : 0;
        int r = g_rowptr[i] + off;
        g_rowptr[i] = r;
        g_cursor[i] = r;
        g_dinv[i] = rsqrtf((float)g_deg[i] + 1.0f);
    }
}

// ---------------------------------------------------------------------------
// Counting-sort edges by dst
__global__ void sort_kernel(const void* __restrict__ ei, int E) {
    int e = blockIdx.x * blockDim.x + threadIdx.x;
    if (e >= E) return;
    int is64 = g_is64;
    int src = load_idx(ei, is64, e);
    int dst = load_idx(ei, is64, (long long)E + e);
    int pos = atomicAdd(&g_cursor[dst], 1);
    g_srcs[pos] = src;
}

// ---------------------------------------------------------------------------
__device__ __forceinline__ void acc_h8(float* acc, uint4 v, float d) {
    __half2 p0 = *reinterpret_cast<__half2*>(&v.x);
    __half2 p1 = *reinterpret_cast<__half2*>(&v.y);
    __half2 p2 = *reinterpret_cast<__half2*>(&v.z);
    __half2 p3 = *reinterpret_cast<__half2*>(&v.w);
    float2 f0 = __half22float2(p0);
    float2 f1 = __half22float2(p1);
    float2 f2 = __half22float2(p2);
    float2 f3 = __half22float2(p3);
    acc[0] = fmaf(d, f0.x, acc[0]); acc[1] = fmaf(d, f0.y, acc[1]);
    acc[2] = fmaf(d, f1.x, acc[2]); acc[3] = fmaf(d, f1.y, acc[3]);
    acc[4] = fmaf(d, f2.x, acc[4]); acc[5] = fmaf(d, f2.y, acc[5]);
    acc[6] = fmaf(d, f3.x, acc[6]); acc[7] = fmaf(d, f3.y, acc[7]);
}

// ---------------------------------------------------------------------------
// Fused gather1 + pointwise + GEMM2.
// Block = 64 nodes, 512 threads. Phase A: 8 lanes/node gather
//   acc = sum dinv[s]*g1h[s], then h = relu(dinv*(acc + dinv*g1h_self) + b1)
//   staged to smem. Phase B: 8 col-groups/node compute g2 = h @ W2 (fp16 out).
#define HS 68   // padded row stride (floats) to dodge bank conflicts
__global__ __launch_bounds__(512) void gather1_gemm2_kernel(
    const float* __restrict__ b1, const float* __restrict__ W2, int nodes)
{
    __shared__ float h_s[64 * HS];
    __shared__ float W2s[C1 * C2];
    __shared__ float b1s[C1];

    int tid = threadIdx.x;
    for (int i = tid; i < C1 * C2; i += 512) W2s[i] = W2[i];
    if (tid < C1) b1s[tid] = b1[tid];

    int nodeBase = blockIdx.x * 64;
    int nl = tid >> 3;          // local node 0..63
    int c  = tid & 7;           // uint4 slice (8 halves)
    int node = nodeBase + nl;

    float acc[8];
    #pragma unroll
    for (int j = 0; j < 8; j++) acc[j] = 0.0f;

    if (node < nodes) {
        int deg = g_deg[node];
        int base = g_rowptr[node];
        const uint4* G = reinterpret_cast<const uint4*>(g_g1h);
        int i = 0;
        for (; i + 4 <= deg; i += 4) {
            int s0 = g_srcs[base + i + 0];
            int s1 = g_srcs[base + i + 1];
            int s2 = g_srcs[base + i + 2];
            int s3 = g_srcs[base + i + 3];
            float d0 = g_dinv[s0], d1 = g_dinv[s1], d2 = g_dinv[s2], d3 = g_dinv[s3];
            uint4 v0 = G[s0 * 8 + c];
            uint4 v1 = G[s1 * 8 + c];
            uint4 v2 = G[s2 * 8 + c];
            uint4 v3 = G[s3 * 8 + c];
            acc_h8(acc, v0, d0);
            acc_h8(acc, v1, d1);
            acc_h8(acc, v2, d2);
            acc_h8(acc, v3, d3);
        }
        for (; i < deg; i++) {
            int s = g_srcs[base + i];
            acc_h8(acc, G[s * 8 + c], g_dinv[s]);
        }
        // self term + bias + relu
        float d = g_dinv[node];
        uint4 gv = G[node * 8 + c];
        float gs[8];
        {
            __half2 p0 = *reinterpret_cast<__half2*>(&gv.x);
            __half2 p1 = *reinterpret_cast<__half2*>(&gv.y);
            __half2 p2 = *reinterpret_cast<__half2*>(&gv.z);
            __half2 p3 = *reinterpret_cast<__half2*>(&gv.w);
            float2 f0 = __half22float2(p0), f1 = __half22float2(p1);
            float2 f2 = __half22float2(p2), f3 = __half22float2(p3);
            gs[0] = f0.x; gs[1] = f0.y; gs[2] = f1.x; gs[3] = f1.y;
            gs[4] = f2.x; gs[5] = f2.y; gs[6] = f3.x; gs[7] = f3.y;
        }
        float* hp = &h_s[nl * HS + c * 8];
        #pragma unroll
        for (int j = 0; j < 8; j++) {
            float hv = fmaf(d, fmaf(d, gs[j], acc[j]), b1s[c * 8 + j]);
            hp[j] = fmaxf(hv, 0.0f);
        }
    }
    __syncthreads();

    // Phase B: GEMM2. thread = (node nl, colgroup cg of 4 cols)
    if (node >= nodes) return;
    int cg = c;                   // 8 groups x 4 cols = 32
    float o0 = 0.f, o1 = 0.f, o2 = 0.f, o3 = 0.f;
    const float* hr = &h_s[nl * HS];
    #pragma unroll 8
    for (int k = 0; k < C1; k++) {
        float hk = hr[k];
        const float* w = &W2s[k * C2 + cg * 4];
        o0 = fmaf(hk, w[0], o0);
        o1 = fmaf(hk, w[1], o1);
        o2 = fmaf(hk, w[2], o2);
        o3 = fmaf(hk, w[3], o3);
    }
    __half2 h0 = __floats2half2_rn(o0, o1);
    __half2 h1 = __floats2half2_rn(o2, o3);
    uint2 o;
    o.x = *reinterpret_cast<unsigned int*>(&h0);
    o.y = *reinterpret_cast<unsigned int*>(&h1);
    reinterpret_cast<uint2*>(g_g2h)[(size_t)node * 8 + cg] = o;
}

// ---------------------------------------------------------------------------
// Fused gather2 + final head.
// Block = 128 nodes, 512 threads, 4 lanes/node (8 channels each).
// p = sum_j relu(dinv*(acc_j + dinv*g2_j) + b2_j) * Wh_j, reduced over 4 lanes.
__global__ __launch_bounds__(512) void gather2_final_kernel(
    const float* __restrict__ b2, const float* __restrict__ Wh,
    const float* __restrict__ bh, float* __restrict__ out, int nodes)
{
    __shared__ float b2s[C2];
    __shared__ float Whs[C2];
    int tid = threadIdx.x;
    if (tid < C2) { b2s[tid] = b2[tid]; Whs[tid] = Wh[tid]; }
    __syncthreads();

    int nl = tid >> 2;
    int c  = tid & 3;
    int node = blockIdx.x * 128 + nl;
    if (node >= nodes) return;

    int deg = g_deg[node];
    int base = g_rowptr[node];
    const uint4* G = reinterpret_cast<const uint4*>(g_g2h);

    float acc[8];
    #pragma unroll
    for (int j = 0; j < 8; j++) acc[j] = 0.0f;

    int i = 0;
    for (; i + 4 <= deg; i += 4) {
        int s0 = g_srcs[base + i + 0];
        int s1 = g_srcs[base + i + 1];
        int s2 = g_srcs[base + i + 2];
        int s3 = g_srcs[base + i + 3];
        float d0 = g_dinv[s0], d1 = g_dinv[s1], d2 = g_dinv[s2], d3 = g_dinv[s3];
        uint4 v0 = G[s0 * 4 + c];
        uint4 v1 = G[s1 * 4 + c];
        uint4 v2 = G[s2 * 4 + c];
        uint4 v3 = G[s3 * 4 + c];
        acc_h8(acc, v0, d0);
        acc_h8(acc, v1, d1);
        acc_h8(acc, v2, d2);
        acc_h8(acc, v3, d3);
    }
    for (; i < deg; i++) {
        int s = g_srcs[base + i];
        acc_h8(acc, G[s * 4 + c], g_dinv[s]);
    }

    float d = g_dinv[node];
    uint4 gv = G[node * 4 + c];
    float gs[8];
    {
        __half2 p0 = *reinterpret_cast<__half2*>(&gv.x);
        __half2 p1 = *reinterpret_cast<__half2*>(&gv.y);
        __half2 p2 = *reinterpret_cast<__half2*>(&gv.z);
        __half2 p3 = *reinterpret_cast<__half2*>(&gv.w);
        float2 f0 = __half22float2(p0), f1 = __half22float2(p1);
        float2 f2 = __half22float2(p2), f3 = __half22float2(p3);
        gs[0] = f0.x; gs[1] = f0.y; gs[2] = f1.x; gs[3] = f1.y;
        gs[4] = f2.x; gs[5] = f2.y; gs[6] = f3.x; gs[7] = f3.y;
    }

    float p = 0.0f;
    #pragma unroll
    for (int j = 0; j < 8; j++) {
        int ch = c * 8 + j;
        float v = fmaf(d, fmaf(d, gs[j], acc[j]), b2s[ch]);
        v = fmaxf(v, 0.0f);
        p = fmaf(v, Whs[ch], p);
    }
    p += __shfl_xor_sync(0xffffffffu, p, 1);
    p += __shfl_xor_sync(0xffffffffu, p, 2);
    if (c == 0) out[node] = p + bh[0];
}

// ---------------------------------------------------------------------------
extern "C" void kernel_launch(void* const* d_in, const int* in_sizes, int n_in,
                              void* d_out, int out_size)
{
    const float* x  = (const float*)d_in[0];
    const void*  ei = d_in[1];
    const float* W1 = (const float*)d_in[2];
    const float* b1 = (const float*)d_in[3];
    const float* W2 = (const float*)d_in[4];
    const float* b2 = (const float*)d_in[5];
    const float* Wh = (const float*)d_in[6];
    const float* bh = (const float*)d_in[7];
    float* out = (float*)d_out;

    int nodes = in_sizes[0] / 128;
    int E = in_sizes[1] / 2;
    int nb = (nodes + 255) / 256;          // 196
    int degB = (E + 255) / 256;            // 6250
    int gemmB = (nodes + 127) / 128;       // 391

    init_kernel<<<nb, 256>>>(ei, W1, nodes);
    deg_gemm1_kernel<<<degB + gemmB, 256>>>(ei, E, x, nodes, degB);
    scan_block_kernel<<<nb, 256>>>(nodes);
    scan_finish_kernel<<<nb, 256>>>(nodes, nb);
    sort_kernel<<<degB, 256>>>(ei, E);
    gather1_gemm2_kernel<<<(nodes + 63) / 64, 512>>>(b1, W2, nodes);
    gather2_final_kernel<<<(nodes + 127) / 128, 512>>>(b2, Wh, bh, out, nodes);
}